// round 3
// baseline (speedup 1.0000x reference)
#include <cuda_runtime.h>

// ============================================================================
// EquivariantSpatialConv: fused 3x3 replicate-pad depthwise spatial average
// + fully-connected CG tensor product (irreps 1x4e + 1x6e) + residual.
//
// R3: coalesced global I/O. Loads ordered by gmem address with LUT-driven
// smem scatter; stores staged through smem then written as aligned STG.128.
// TP stage (compile-time CG immediates, symmetry-merged) unchanged from R2.
// ============================================================================

#define DEVHOST __host__ __device__

// ---------------- compile-time scalar math ----------------
DEVHOST constexpr double cfact(int n) {
    double r = 1.0;
    for (int i = 2; i <= n; ++i) r *= (double)i;
    return r;
}

DEVHOST constexpr double csqrt(double x) {
    if (x <= 0.0) return 0.0;
    double g = x > 1.0 ? x : 1.0;
    for (int it = 0; it < 48; ++it) g = 0.5 * (g + x / g);
    return g;
}

struct CD { double re, im; };
DEVHOST constexpr CD cmul(CD a, CD b) {
    return CD{a.re * b.re - a.im * b.im, a.re * b.im + a.im * b.re};
}
DEVHOST constexpr CD cconj(CD a) { return CD{a.re, -a.im}; }

DEVHOST constexpr double su2_cg(int j1, int j2, int j3, int m1, int m2, int m3) {
    if (m3 != m1 + m2) return 0.0;
    if (m1 < -j1 || m1 > j1 || m2 < -j2 || m2 > j2 || m3 < -j3 || m3 > j3) return 0.0;
    double pref0 = (2.0 * j3 + 1.0) * cfact(j1 + j2 - j3) * cfact(j1 - j2 + j3) *
                   cfact(-j1 + j2 + j3) / cfact(j1 + j2 + j3 + 1);
    double pref = csqrt(pref0 * cfact(j3 + m3) * cfact(j3 - m3) * cfact(j1 - m1) *
                        cfact(j1 + m1) * cfact(j2 - m2) * cfact(j2 + m2));
    int kmin = 0;
    if (-(j3 - j2 + m1) > kmin) kmin = -(j3 - j2 + m1);
    if (-(j3 - j1 - m2) > kmin) kmin = -(j3 - j1 - m2);
    int kmax = j1 + j2 - j3;
    if (j1 - m1 < kmax) kmax = j1 - m1;
    if (j2 + m2 < kmax) kmax = j2 + m2;
    double s = 0.0;
    for (int k = kmin; k <= kmax; ++k) {
        double d = cfact(k) * cfact(j1 + j2 - j3 - k) * cfact(j1 - m1 - k) *
                   cfact(j2 + m2 - k) * cfact(j3 - j2 + m1 + k) * cfact(j3 - j1 - m2 + k);
        s += ((k & 1) ? -1.0 : 1.0) / d;
    }
    return pref * s;
}

DEVHOST constexpr CD qent(int l, int r, int c) {
    constexpr double S2 = 0.70710678118654752440;
    int m = r - l;
    CD v{0.0, 0.0};
    if (m < 0) {
        if (c == l - m)      v = CD{S2, 0.0};
        else if (c == l + m) v = CD{0.0, -S2};
    } else if (m == 0) {
        if (c == l) v = CD{1.0, 0.0};
    } else {
        double sg = (m & 1) ? -1.0 : 1.0;
        if (c == l + m)      v = CD{sg * S2, 0.0};
        else if (c == l - m) v = CD{0.0, sg * S2};
    }
    int ph = l & 3;
    CD f = (ph == 0) ? CD{1, 0} : (ph == 1) ? CD{0, -1} : (ph == 2) ? CD{-1, 0} : CD{0, 1};
    return cmul(v, f);
}

DEVHOST constexpr double real_cg_entry(int l1, int l2, int l3, int a, int b, int c) {
    int d1 = a >= l1 ? a - l1 : l1 - a;
    int d2 = b >= l2 ? b - l2 : l2 - b;
    int d3 = c >= l3 ? c - l3 : l3 - c;
    CD sum{0.0, 0.0};
    int ni = d1 ? 2 : 1;
    int nk = d2 ? 2 : 1;
    for (int si = 0; si < ni; ++si) {
        int i = d1 ? (si ? l1 + d1 : l1 - d1) : l1;
        int m1 = i - l1;
        CD q1 = qent(l1, i, a);
        for (int sk = 0; sk < nk; ++sk) {
            int k = d2 ? (sk ? l2 + d2 : l2 - d2) : l2;
            int m2 = k - l2;
            int m3 = m1 + m2;
            if (m3 < -l3 || m3 > l3) continue;
            int am3 = m3 < 0 ? -m3 : m3;
            if (am3 != d3) continue;
            int n = l3 + m3;
            CD q2 = qent(l2, k, b);
            CD q3 = cconj(qent(l3, c, n));
            double C = su2_cg(l1, l2, l3, m1, m2, m3);
            CD t = cmul(cmul(q1, q2), q3);
            sum.re += t.re * C;
            sum.im += t.im * C;
        }
    }
    return sum.re;
}

template <int L1, int L2, int L3>
struct CGT {
    float v[2 * L1 + 1][2 * L2 + 1][2 * L3 + 1];
};

template <int L1, int L2, int L3>
DEVHOST constexpr CGT<L1, L2, L3> make_cg() {
    double tmp[2 * L1 + 1][2 * L2 + 1][2 * L3 + 1] = {};
    double ss = 0.0;
    for (int a = 0; a < 2 * L1 + 1; ++a)
        for (int b = 0; b < 2 * L2 + 1; ++b)
            for (int c = 0; c < 2 * L3 + 1; ++c) {
                double e = real_cg_entry(L1, L2, L3, a, b, c);
                tmp[a][b][c] = e;
                ss += e * e;
            }
    double inv = 1.0 / csqrt(ss);
    CGT<L1, L2, L3> r{};
    for (int a = 0; a < 2 * L1 + 1; ++a)
        for (int b = 0; b < 2 * L2 + 1; ++b)
            for (int c = 0; c < 2 * L3 + 1; ++c)
                r.v[a][b][c] = (float)(tmp[a][b][c] * inv);
    return r;
}

// ---------------- compile-time unrolling helpers ----------------
template <int V> struct IC { static constexpr int value = V; };

template <int N, int I = 0, class F>
__device__ __forceinline__ void sfor(F&& f) {
    if constexpr (I < N) {
        f(IC<I>{});
        sfor<N, I + 1>(static_cast<F&&>(f));
    }
}

template <class T>
DEVHOST constexpr bool rowany(const T& t, int a, int b, int dk) {
    for (int k = 0; k < dk; ++k)
        if (t.v[a][b][k] != 0.0f) return true;
    return false;
}
template <class T>
DEVHOST constexpr bool rowany2(const T& t, int a, int b, int dk) {
    for (int k = 0; k < dk; ++k)
        if (t.v[a][b][k] != 0.0f || t.v[b][a][k] != 0.0f) return true;
    return false;
}
template <class T>
DEVHOST constexpr bool symk(const T& t, int a, int b, int dk) {
    for (int k = 0; k < dk; ++k)
        if (t.v[a][b][k] != t.v[b][a][k]) return false;
    return true;
}
template <class TA, class TB>
DEVHOST constexpr bool eqk(const TA& A, int i, int j, const TB& B, int bi, int bj, int dk) {
    for (int k = 0; k < dk; ++k)
        if (A.v[i][j][k] != B.v[bi][bj][k]) return false;
    return true;
}

// ---------------- packed f32x2 helpers ----------------
__device__ __forceinline__ float2 f2fma(float2 a, float2 b, float2 c) {
    float2 d;
    asm("fma.rn.f32x2 %0, %1, %2, %3;"
        : "=l"(*reinterpret_cast<unsigned long long*>(&d))
        : "l"(*reinterpret_cast<unsigned long long*>(&a)),
          "l"(*reinterpret_cast<unsigned long long*>(&b)),
          "l"(*reinterpret_cast<unsigned long long*>(&c)));
    return d;
}
__device__ __forceinline__ float2 f2mul(float2 a, float2 b) {
    float2 d;
    asm("mul.rn.f32x2 %0, %1, %2;"
        : "=l"(*reinterpret_cast<unsigned long long*>(&d))
        : "l"(*reinterpret_cast<unsigned long long*>(&a)),
          "l"(*reinterpret_cast<unsigned long long*>(&b)));
    return d;
}

// ---------------- merged tensor-product blocks ----------------
template <int L, int O>
__device__ __forceinline__ void tp_diag(const float* __restrict__ x1,
                                        const float* __restrict__ x2,
                                        float* __restrict__ acc,
                                        float w0, float w1) {
    constexpr int D = 2 * L + 1;
    constexpr CGT<L, L, 4> C0 = make_cg<L, L, 4>();
    constexpr CGT<L, L, 6> C1 = make_cg<L, L, 6>();
    sfor<D>([&](auto I) {
        constexpr int i = decltype(I)::value;
        sfor<D>([&](auto J) {
            constexpr int j = decltype(J)::value;
            if constexpr (j >= i) {
                constexpr bool l0 = rowany2(C0, i, j, 9);
                constexpr bool l1 = rowany2(C1, i, j, 13);
                if constexpr (l0 || l1) {
                    if constexpr (i == j) {
                        float p = x1[O + i] * x2[O + i];
                        if constexpr (l0) {
                            float t = p * w0;
                            sfor<9>([&](auto K) {
                                constexpr int k = decltype(K)::value;
                                constexpr float cv = C0.v[i][i][k];
                                if constexpr (cv != 0.0f) acc[k] = __fmaf_rn(cv, t, acc[k]);
                            });
                        }
                        if constexpr (l1) {
                            float t = p * w1;
                            sfor<13>([&](auto K) {
                                constexpr int k = decltype(K)::value;
                                constexpr float cv = C1.v[i][i][k];
                                if constexpr (cv != 0.0f) acc[9 + k] = __fmaf_rn(cv, t, acc[9 + k]);
                            });
                        }
                    } else {
                        constexpr bool s0 = symk(C0, i, j, 9);
                        constexpr bool s1 = symk(C1, i, j, 13);
                        if constexpr (s0 && s1) {
                            float s = __fmaf_rn(x1[O + j], x2[O + i], x1[O + i] * x2[O + j]);
                            if constexpr (l0) {
                                float t = s * w0;
                                sfor<9>([&](auto K) {
                                    constexpr int k = decltype(K)::value;
                                    constexpr float cv = C0.v[i][j][k];
                                    if constexpr (cv != 0.0f) acc[k] = __fmaf_rn(cv, t, acc[k]);
                                });
                            }
                            if constexpr (l1) {
                                float t = s * w1;
                                sfor<13>([&](auto K) {
                                    constexpr int k = decltype(K)::value;
                                    constexpr float cv = C1.v[i][j][k];
                                    if constexpr (cv != 0.0f) acc[9 + k] = __fmaf_rn(cv, t, acc[9 + k]);
                                });
                            }
                        } else {
                            float p1 = x1[O + i] * x2[O + j];
                            float p2 = x1[O + j] * x2[O + i];
                            if constexpr (l0) {
                                float t1 = p1 * w0, t2 = p2 * w0;
                                sfor<9>([&](auto K) {
                                    constexpr int k = decltype(K)::value;
                                    constexpr float c1 = C0.v[i][j][k];
                                    constexpr float c2 = C0.v[j][i][k];
                                    if constexpr (c1 != 0.0f) acc[k] = __fmaf_rn(c1, t1, acc[k]);
                                    if constexpr (c2 != 0.0f) acc[k] = __fmaf_rn(c2, t2, acc[k]);
                                });
                            }
                            if constexpr (l1) {
                                float t1 = p1 * w1, t2 = p2 * w1;
                                sfor<13>([&](auto K) {
                                    constexpr int k = decltype(K)::value;
                                    constexpr float c1 = C1.v[i][j][k];
                                    constexpr float c2 = C1.v[j][i][k];
                                    if constexpr (c1 != 0.0f) acc[9 + k] = __fmaf_rn(c1, t1, acc[9 + k]);
                                    if constexpr (c2 != 0.0f) acc[9 + k] = __fmaf_rn(c2, t2, acc[9 + k]);
                                });
                            }
                        }
                    }
                }
            }
        });
    });
}

__device__ __forceinline__ void tp_cross(const float* __restrict__ x1,
                                         const float* __restrict__ x2,
                                         float* __restrict__ acc,
                                         float wA0, float wA1, float wB0, float wB1) {
    constexpr CGT<4, 6, 4> A0 = make_cg<4, 6, 4>();
    constexpr CGT<4, 6, 6> A1 = make_cg<4, 6, 6>();
    constexpr CGT<6, 4, 4> B0 = make_cg<6, 4, 4>();
    constexpr CGT<6, 4, 6> B1 = make_cg<6, 4, 6>();
    sfor<9>([&](auto I) {
        constexpr int i = decltype(I)::value;
        sfor<13>([&](auto J) {
            constexpr int j = decltype(J)::value;
            constexpr bool a0 = rowany(A0, i, j, 9);
            constexpr bool b0 = rowany(B0, j, i, 9);
            constexpr bool a1 = rowany(A1, i, j, 13);
            constexpr bool b1 = rowany(B1, j, i, 13);
            if constexpr (a0 || b0 || a1 || b1) {
                float p1 = x1[i] * x2[9 + j];
                float p2 = x2[i] * x1[9 + j];
                if constexpr (a0 || b0) {
                    constexpr bool e = eqk(A0, i, j, B0, j, i, 9);
                    if constexpr (e) {
                        float u = __fmaf_rn(wB0, p2, p1 * wA0);
                        sfor<9>([&](auto K) {
                            constexpr int k = decltype(K)::value;
                            constexpr float cv = A0.v[i][j][k];
                            if constexpr (cv != 0.0f) acc[k] = __fmaf_rn(cv, u, acc[k]);
                        });
                    } else {
                        if constexpr (a0) {
                            float t1 = p1 * wA0;
                            sfor<9>([&](auto K) {
                                constexpr int k = decltype(K)::value;
                                constexpr float cv = A0.v[i][j][k];
                                if constexpr (cv != 0.0f) acc[k] = __fmaf_rn(cv, t1, acc[k]);
                            });
                        }
                        if constexpr (b0) {
                            float t2 = p2 * wB0;
                            sfor<9>([&](auto K) {
                                constexpr int k = decltype(K)::value;
                                constexpr float cv = B0.v[j][i][k];
                                if constexpr (cv != 0.0f) acc[k] = __fmaf_rn(cv, t2, acc[k]);
                            });
                        }
                    }
                }
                if constexpr (a1 || b1) {
                    constexpr bool e = eqk(A1, i, j, B1, j, i, 13);
                    if constexpr (e) {
                        float u = __fmaf_rn(wB1, p2, p1 * wA1);
                        sfor<13>([&](auto K) {
                            constexpr int k = decltype(K)::value;
                            constexpr float cv = A1.v[i][j][k];
                            if constexpr (cv != 0.0f) acc[9 + k] = __fmaf_rn(cv, u, acc[9 + k]);
                        });
                    } else {
                        if constexpr (a1) {
                            float t1 = p1 * wA1;
                            sfor<13>([&](auto K) {
                                constexpr int k = decltype(K)::value;
                                constexpr float cv = A1.v[i][j][k];
                                if constexpr (cv != 0.0f) acc[9 + k] = __fmaf_rn(cv, t1, acc[9 + k]);
                            });
                        }
                        if constexpr (b1) {
                            float t2 = p2 * wB1;
                            sfor<13>([&](auto K) {
                                constexpr int k = decltype(K)::value;
                                constexpr float cv = B1.v[j][i][k];
                                if constexpr (cv != 0.0f) acc[9 + k] = __fmaf_rn(cv, t2, acc[9 + k]);
                            });
                        }
                    }
                }
            }
        });
    });
}

// ---------------- kernel ----------------
constexpr int H = 768, W = 768;
constexpr int TX = 32, TY = 8;             // 256-thread tile
constexpr int HTX = TX + 2, HTY = TY + 2;  // 34 x 10 haloed tile
constexpr int NPIX = HTX * HTY;            // 340
constexpr int NPAIR = 11;
constexpr int RSTR = 23;                   // res stride (odd -> conflict-free)

__global__ void __launch_bounds__(256) eq_spatial_tp_kernel(
    const float* __restrict__ f4, const float* __restrict__ f6,
    const float* __restrict__ sw, const float* __restrict__ wp,
    float* __restrict__ out4, float* __restrict__ out6) {
    // channel-pair-major halo tile; aliased by the output staging buffer.
    __shared__ float2 tile[NPAIR * NPIX];   // 29920 B; res needs 256*23*4=23552 B
    __shared__ int2 rowlut[HTY];            // {gy*6912, gy*9984}
    __shared__ int2 glut4[HTX * 9];         // {gmem off within row, smem word off}
    __shared__ int2 glut6[HTX * 13];
    __shared__ int4 slut4[72];              // res word offsets for out4 float4s
    __shared__ int4 slut6[104];

    float* smf = reinterpret_cast<float*>(tile);
    float* resf = reinterpret_cast<float*>(tile);

    const int tid = threadIdx.x;
    const int bx = blockIdx.x, by = blockIdx.y;
    const int gx0 = bx * TX - 1, gy0 = by * TY - 1;

    // ---- phase 0: build LUTs ----
    for (int t = tid; t < HTX * 9; t += 256) {
        int col = t / 9, ch = t - 9 * col;
        int gx = gx0 + col; gx = gx < 0 ? 0 : (gx > W - 1 ? W - 1 : gx);
        glut4[t] = make_int2(gx * 9 + ch, (ch >> 1) * (2 * NPIX) + (ch & 1) + col * 2);
    }
    for (int t = tid; t < HTX * 13; t += 256) {
        int col = t / 13, ch = t - 13 * col;
        int gx = gx0 + col; gx = gx < 0 ? 0 : (gx > W - 1 ? W - 1 : gx);
        int gch = 9 + ch;
        glut6[t] = make_int2(gx * 13 + ch, (gch >> 1) * (2 * NPIX) + (gch & 1) + col * 2);
    }
    if (tid < HTY) {
        int gy = gy0 + tid; gy = gy < 0 ? 0 : (gy > H - 1 ? H - 1 : gy);
        rowlut[tid] = make_int2(gy * (W * 9), gy * (W * 13));
    }
    if (tid < 72) {
        int fl = tid * 4;
        slut4[tid] = make_int4(((fl + 0) / 9) * RSTR + (fl + 0) % 9,
                               ((fl + 1) / 9) * RSTR + (fl + 1) % 9,
                               ((fl + 2) / 9) * RSTR + (fl + 2) % 9,
                               ((fl + 3) / 9) * RSTR + (fl + 3) % 9);
    }
    if (tid >= 128 && tid < 232) {
        int q = tid - 128;
        int fl = q * 4;
        slut6[q] = make_int4(((fl + 0) / 13) * RSTR + 9 + (fl + 0) % 13,
                             ((fl + 1) / 13) * RSTR + 9 + (fl + 1) % 13,
                             ((fl + 2) / 13) * RSTR + 9 + (fl + 2) % 13,
                             ((fl + 3) / 13) * RSTR + 9 + (fl + 3) % 13);
    }
    __syncthreads();

    // ---- phase 1: coalesced halo-tile load (gmem-address ordered) ----
    for (int e = tid; e < HTY * HTX * 9; e += 256) {
        int row = e / (HTX * 9), i = e - row * (HTX * 9);
        int2 rb = rowlut[row];
        int2 g = glut4[i];
        smf[g.y + row * (2 * HTX)] = f4[rb.x + g.x];
    }
    for (int e = tid; e < HTY * HTX * 13; e += 256) {
        int row = e / (HTX * 13), i = e - row * (HTX * 13);
        int2 rb = rowlut[row];
        int2 g = glut6[i];
        smf[g.y + row * (2 * HTX)] = f6[rb.y + g.x];
    }
    __syncthreads();

    float2 swp[9];
#pragma unroll
    for (int q = 0; q < 9; ++q) {
        float s = sw[q];
        swp[q] = make_float2(s, s);
    }
    float wcomb[8];
#pragma unroll
    for (int p = 0; p < 8; ++p) wcomb[p] = 0.5f * wp[p];  // ALPHA = 1/sqrt(4)

    const int tx = tid & 31, ty = tid >> 5;

    // ---- phase 2: spatial average (packed f32x2) + tensor product ----
    __align__(8) float x1[22], x2[22];
    float2* x1v = reinterpret_cast<float2*>(x1);
    float2* x2v = reinterpret_cast<float2*>(x2);
    {
        const int cpix = (ty + 1) * HTX + (tx + 1);
#pragma unroll
        for (int p = 0; p < NPAIR; ++p) {
            x1v[p] = tile[p * NPIX + cpix];
            x2v[p] = f2mul(swp[4], x1v[p]);
        }
    }
#pragma unroll
    for (int dy = 0; dy < 3; ++dy)
#pragma unroll
        for (int dx = 0; dx < 3; ++dx) {
            if (dy == 1 && dx == 1) continue;
            const int npix = (ty + dy) * HTX + (tx + dx);
            const float2 wq = swp[dy * 3 + dx];
#pragma unroll
            for (int p = 0; p < NPAIR; ++p)
                x2v[p] = f2fma(wq, tile[p * NPIX + npix], x2v[p]);
        }

    float acc[22];
#pragma unroll
    for (int k = 0; k < 22; ++k) acc[k] = x1[k];  // residual folded into init

    tp_diag<4, 0>(x1, x2, acc, wcomb[0], wcomb[1]);
    tp_cross(x1, x2, acc, wcomb[2], wcomb[3], wcomb[4], wcomb[5]);
    tp_diag<6, 9>(x1, x2, acc, wcomb[6], wcomb[7]);

    // ---- phase 3: stage results pixel-major (conflict-free stride-23) ----
    __syncthreads();  // all tile reads complete before aliasing as res
    {
        const int base = tid * RSTR;
#pragma unroll
        for (int k = 0; k < 22; ++k) resf[base + k] = acc[k];
    }
    __syncthreads();

    // ---- phase 4: coalesced aligned STG.128 stores ----
    // out4 block region: 8 rows x 288 contiguous floats (16B-aligned)
    {
        const int obase4 = (by * TY * W + bx * TX) * 9;
        for (int e = tid; e < 8 * 72; e += 256) {
            int row = e / 72, q = e - row * 72;
            int4 s = slut4[q];
            int rb = row * (TX * RSTR);
            float4 v = make_float4(resf[rb + s.x], resf[rb + s.y],
                                   resf[rb + s.z], resf[rb + s.w]);
            reinterpret_cast<float4*>(out4 + obase4 + row * (W * 9))[q] = v;
        }
    }
    // out6 block region: 8 rows x 416 contiguous floats (16B-aligned)
    {
        const int obase6 = (by * TY * W + bx * TX) * 13;
        for (int e = tid; e < 8 * 104; e += 256) {
            int row = e / 104, q = e - row * 104;
            int4 s = slut6[q];
            int rb = row * (TX * RSTR);
            float4 v = make_float4(resf[rb + s.x], resf[rb + s.y],
                                   resf[rb + s.z], resf[rb + s.w]);
            reinterpret_cast<float4*>(out6 + obase6 + row * (W * 13))[q] = v;
        }
    }
}

extern "C" void kernel_launch(void* const* d_in, const int* in_sizes, int n_in,
                              void* d_out, int out_size) {
    const float* f4 = (const float*)d_in[0];
    const float* f6 = (const float*)d_in[1];
    const float* sw = (const float*)d_in[2];  // spatial_weights [3,3]
    const float* wp = (const float*)d_in[3];  // w_paths [8]
    float* out = (float*)d_out;
    const size_t N = (size_t)H * W;

    dim3 grid(W / TX, H / TY);  // 24 x 96
    eq_spatial_tp_kernel<<<grid, 256>>>(f4, f6, sw, wp, out, out + N * 9);
}

// round 4
// speedup vs baseline: 1.2263x; 1.2263x over previous
#include <cuda_runtime.h>

// ============================================================================
// EquivariantSpatialConv: fused 3x3 replicate-pad depthwise spatial average
// + fully-connected CG tensor product (irreps 1x4e + 1x6e) + residual.
//
// R4: 128-thread CTAs (32x4 tile), __launch_bounds__(128,7) -> 7 CTAs/SM.
// More independent CTAs per SM desynchronize the load/compute/store phases
// (R2/R3 were phase-locked at 3 CTAs/SM). TP stage unchanged from R2.
// ============================================================================

#define DEVHOST __host__ __device__

// ---------------- compile-time scalar math ----------------
DEVHOST constexpr double cfact(int n) {
    double r = 1.0;
    for (int i = 2; i <= n; ++i) r *= (double)i;
    return r;
}

DEVHOST constexpr double csqrt(double x) {
    if (x <= 0.0) return 0.0;
    double g = x > 1.0 ? x : 1.0;
    for (int it = 0; it < 48; ++it) g = 0.5 * (g + x / g);
    return g;
}

struct CD { double re, im; };
DEVHOST constexpr CD cmul(CD a, CD b) {
    return CD{a.re * b.re - a.im * b.im, a.re * b.im + a.im * b.re};
}
DEVHOST constexpr CD cconj(CD a) { return CD{a.re, -a.im}; }

DEVHOST constexpr double su2_cg(int j1, int j2, int j3, int m1, int m2, int m3) {
    if (m3 != m1 + m2) return 0.0;
    if (m1 < -j1 || m1 > j1 || m2 < -j2 || m2 > j2 || m3 < -j3 || m3 > j3) return 0.0;
    double pref0 = (2.0 * j3 + 1.0) * cfact(j1 + j2 - j3) * cfact(j1 - j2 + j3) *
                   cfact(-j1 + j2 + j3) / cfact(j1 + j2 + j3 + 1);
    double pref = csqrt(pref0 * cfact(j3 + m3) * cfact(j3 - m3) * cfact(j1 - m1) *
                        cfact(j1 + m1) * cfact(j2 - m2) * cfact(j2 + m2));
    int kmin = 0;
    if (-(j3 - j2 + m1) > kmin) kmin = -(j3 - j2 + m1);
    if (-(j3 - j1 - m2) > kmin) kmin = -(j3 - j1 - m2);
    int kmax = j1 + j2 - j3;
    if (j1 - m1 < kmax) kmax = j1 - m1;
    if (j2 + m2 < kmax) kmax = j2 + m2;
    double s = 0.0;
    for (int k = kmin; k <= kmax; ++k) {
        double d = cfact(k) * cfact(j1 + j2 - j3 - k) * cfact(j1 - m1 - k) *
                   cfact(j2 + m2 - k) * cfact(j3 - j2 + m1 + k) * cfact(j3 - j1 - m2 + k);
        s += ((k & 1) ? -1.0 : 1.0) / d;
    }
    return pref * s;
}

DEVHOST constexpr CD qent(int l, int r, int c) {
    constexpr double S2 = 0.70710678118654752440;
    int m = r - l;
    CD v{0.0, 0.0};
    if (m < 0) {
        if (c == l - m)      v = CD{S2, 0.0};
        else if (c == l + m) v = CD{0.0, -S2};
    } else if (m == 0) {
        if (c == l) v = CD{1.0, 0.0};
    } else {
        double sg = (m & 1) ? -1.0 : 1.0;
        if (c == l + m)      v = CD{sg * S2, 0.0};
        else if (c == l - m) v = CD{0.0, sg * S2};
    }
    int ph = l & 3;
    CD f = (ph == 0) ? CD{1, 0} : (ph == 1) ? CD{0, -1} : (ph == 2) ? CD{-1, 0} : CD{0, 1};
    return cmul(v, f);
}

DEVHOST constexpr double real_cg_entry(int l1, int l2, int l3, int a, int b, int c) {
    int d1 = a >= l1 ? a - l1 : l1 - a;
    int d2 = b >= l2 ? b - l2 : l2 - b;
    int d3 = c >= l3 ? c - l3 : l3 - c;
    CD sum{0.0, 0.0};
    int ni = d1 ? 2 : 1;
    int nk = d2 ? 2 : 1;
    for (int si = 0; si < ni; ++si) {
        int i = d1 ? (si ? l1 + d1 : l1 - d1) : l1;
        int m1 = i - l1;
        CD q1 = qent(l1, i, a);
        for (int sk = 0; sk < nk; ++sk) {
            int k = d2 ? (sk ? l2 + d2 : l2 - d2) : l2;
            int m2 = k - l2;
            int m3 = m1 + m2;
            if (m3 < -l3 || m3 > l3) continue;
            int am3 = m3 < 0 ? -m3 : m3;
            if (am3 != d3) continue;
            int n = l3 + m3;
            CD q2 = qent(l2, k, b);
            CD q3 = cconj(qent(l3, c, n));
            double C = su2_cg(l1, l2, l3, m1, m2, m3);
            CD t = cmul(cmul(q1, q2), q3);
            sum.re += t.re * C;
            sum.im += t.im * C;
        }
    }
    return sum.re;
}

template <int L1, int L2, int L3>
struct CGT {
    float v[2 * L1 + 1][2 * L2 + 1][2 * L3 + 1];
};

template <int L1, int L2, int L3>
DEVHOST constexpr CGT<L1, L2, L3> make_cg() {
    double tmp[2 * L1 + 1][2 * L2 + 1][2 * L3 + 1] = {};
    double ss = 0.0;
    for (int a = 0; a < 2 * L1 + 1; ++a)
        for (int b = 0; b < 2 * L2 + 1; ++b)
            for (int c = 0; c < 2 * L3 + 1; ++c) {
                double e = real_cg_entry(L1, L2, L3, a, b, c);
                tmp[a][b][c] = e;
                ss += e * e;
            }
    double inv = 1.0 / csqrt(ss);
    CGT<L1, L2, L3> r{};
    for (int a = 0; a < 2 * L1 + 1; ++a)
        for (int b = 0; b < 2 * L2 + 1; ++b)
            for (int c = 0; c < 2 * L3 + 1; ++c)
                r.v[a][b][c] = (float)(tmp[a][b][c] * inv);
    return r;
}

// ---------------- compile-time unrolling helpers ----------------
template <int V> struct IC { static constexpr int value = V; };

template <int N, int I = 0, class F>
__device__ __forceinline__ void sfor(F&& f) {
    if constexpr (I < N) {
        f(IC<I>{});
        sfor<N, I + 1>(static_cast<F&&>(f));
    }
}

template <class T>
DEVHOST constexpr bool rowany(const T& t, int a, int b, int dk) {
    for (int k = 0; k < dk; ++k)
        if (t.v[a][b][k] != 0.0f) return true;
    return false;
}
template <class T>
DEVHOST constexpr bool rowany2(const T& t, int a, int b, int dk) {
    for (int k = 0; k < dk; ++k)
        if (t.v[a][b][k] != 0.0f || t.v[b][a][k] != 0.0f) return true;
    return false;
}
template <class T>
DEVHOST constexpr bool symk(const T& t, int a, int b, int dk) {
    for (int k = 0; k < dk; ++k)
        if (t.v[a][b][k] != t.v[b][a][k]) return false;
    return true;
}
template <class TA, class TB>
DEVHOST constexpr bool eqk(const TA& A, int i, int j, const TB& B, int bi, int bj, int dk) {
    for (int k = 0; k < dk; ++k)
        if (A.v[i][j][k] != B.v[bi][bj][k]) return false;
    return true;
}

// ---------------- packed f32x2 helpers ----------------
__device__ __forceinline__ float2 f2fma(float2 a, float2 b, float2 c) {
    float2 d;
    asm("fma.rn.f32x2 %0, %1, %2, %3;"
        : "=l"(*reinterpret_cast<unsigned long long*>(&d))
        : "l"(*reinterpret_cast<unsigned long long*>(&a)),
          "l"(*reinterpret_cast<unsigned long long*>(&b)),
          "l"(*reinterpret_cast<unsigned long long*>(&c)));
    return d;
}
__device__ __forceinline__ float2 f2mul(float2 a, float2 b) {
    float2 d;
    asm("mul.rn.f32x2 %0, %1, %2;"
        : "=l"(*reinterpret_cast<unsigned long long*>(&d))
        : "l"(*reinterpret_cast<unsigned long long*>(&a)),
          "l"(*reinterpret_cast<unsigned long long*>(&b)));
    return d;
}

// ---------------- merged tensor-product blocks ----------------
template <int L, int O>
__device__ __forceinline__ void tp_diag(const float* __restrict__ x1,
                                        const float* __restrict__ x2,
                                        float* __restrict__ acc,
                                        float w0, float w1) {
    constexpr int D = 2 * L + 1;
    constexpr CGT<L, L, 4> C0 = make_cg<L, L, 4>();
    constexpr CGT<L, L, 6> C1 = make_cg<L, L, 6>();
    sfor<D>([&](auto I) {
        constexpr int i = decltype(I)::value;
        sfor<D>([&](auto J) {
            constexpr int j = decltype(J)::value;
            if constexpr (j >= i) {
                constexpr bool l0 = rowany2(C0, i, j, 9);
                constexpr bool l1 = rowany2(C1, i, j, 13);
                if constexpr (l0 || l1) {
                    if constexpr (i == j) {
                        float p = x1[O + i] * x2[O + i];
                        if constexpr (l0) {
                            float t = p * w0;
                            sfor<9>([&](auto K) {
                                constexpr int k = decltype(K)::value;
                                constexpr float cv = C0.v[i][i][k];
                                if constexpr (cv != 0.0f) acc[k] = __fmaf_rn(cv, t, acc[k]);
                            });
                        }
                        if constexpr (l1) {
                            float t = p * w1;
                            sfor<13>([&](auto K) {
                                constexpr int k = decltype(K)::value;
                                constexpr float cv = C1.v[i][i][k];
                                if constexpr (cv != 0.0f) acc[9 + k] = __fmaf_rn(cv, t, acc[9 + k]);
                            });
                        }
                    } else {
                        constexpr bool s0 = symk(C0, i, j, 9);
                        constexpr bool s1 = symk(C1, i, j, 13);
                        if constexpr (s0 && s1) {
                            float s = __fmaf_rn(x1[O + j], x2[O + i], x1[O + i] * x2[O + j]);
                            if constexpr (l0) {
                                float t = s * w0;
                                sfor<9>([&](auto K) {
                                    constexpr int k = decltype(K)::value;
                                    constexpr float cv = C0.v[i][j][k];
                                    if constexpr (cv != 0.0f) acc[k] = __fmaf_rn(cv, t, acc[k]);
                                });
                            }
                            if constexpr (l1) {
                                float t = s * w1;
                                sfor<13>([&](auto K) {
                                    constexpr int k = decltype(K)::value;
                                    constexpr float cv = C1.v[i][j][k];
                                    if constexpr (cv != 0.0f) acc[9 + k] = __fmaf_rn(cv, t, acc[9 + k]);
                                });
                            }
                        } else {
                            float p1 = x1[O + i] * x2[O + j];
                            float p2 = x1[O + j] * x2[O + i];
                            if constexpr (l0) {
                                float t1 = p1 * w0, t2 = p2 * w0;
                                sfor<9>([&](auto K) {
                                    constexpr int k = decltype(K)::value;
                                    constexpr float c1 = C0.v[i][j][k];
                                    constexpr float c2 = C0.v[j][i][k];
                                    if constexpr (c1 != 0.0f) acc[k] = __fmaf_rn(c1, t1, acc[k]);
                                    if constexpr (c2 != 0.0f) acc[k] = __fmaf_rn(c2, t2, acc[k]);
                                });
                            }
                            if constexpr (l1) {
                                float t1 = p1 * w1, t2 = p2 * w1;
                                sfor<13>([&](auto K) {
                                    constexpr int k = decltype(K)::value;
                                    constexpr float c1 = C1.v[i][j][k];
                                    constexpr float c2 = C1.v[j][i][k];
                                    if constexpr (c1 != 0.0f) acc[9 + k] = __fmaf_rn(c1, t1, acc[9 + k]);
                                    if constexpr (c2 != 0.0f) acc[9 + k] = __fmaf_rn(c2, t2, acc[9 + k]);
                                });
                            }
                        }
                    }
                }
            }
        });
    });
}

__device__ __forceinline__ void tp_cross(const float* __restrict__ x1,
                                         const float* __restrict__ x2,
                                         float* __restrict__ acc,
                                         float wA0, float wA1, float wB0, float wB1) {
    constexpr CGT<4, 6, 4> A0 = make_cg<4, 6, 4>();
    constexpr CGT<4, 6, 6> A1 = make_cg<4, 6, 6>();
    constexpr CGT<6, 4, 4> B0 = make_cg<6, 4, 4>();
    constexpr CGT<6, 4, 6> B1 = make_cg<6, 4, 6>();
    sfor<9>([&](auto I) {
        constexpr int i = decltype(I)::value;
        sfor<13>([&](auto J) {
            constexpr int j = decltype(J)::value;
            constexpr bool a0 = rowany(A0, i, j, 9);
            constexpr bool b0 = rowany(B0, j, i, 9);
            constexpr bool a1 = rowany(A1, i, j, 13);
            constexpr bool b1 = rowany(B1, j, i, 13);
            if constexpr (a0 || b0 || a1 || b1) {
                float p1 = x1[i] * x2[9 + j];
                float p2 = x2[i] * x1[9 + j];
                if constexpr (a0 || b0) {
                    constexpr bool e = eqk(A0, i, j, B0, j, i, 9);
                    if constexpr (e) {
                        float u = __fmaf_rn(wB0, p2, p1 * wA0);
                        sfor<9>([&](auto K) {
                            constexpr int k = decltype(K)::value;
                            constexpr float cv = A0.v[i][j][k];
                            if constexpr (cv != 0.0f) acc[k] = __fmaf_rn(cv, u, acc[k]);
                        });
                    } else {
                        if constexpr (a0) {
                            float t1 = p1 * wA0;
                            sfor<9>([&](auto K) {
                                constexpr int k = decltype(K)::value;
                                constexpr float cv = A0.v[i][j][k];
                                if constexpr (cv != 0.0f) acc[k] = __fmaf_rn(cv, t1, acc[k]);
                            });
                        }
                        if constexpr (b0) {
                            float t2 = p2 * wB0;
                            sfor<9>([&](auto K) {
                                constexpr int k = decltype(K)::value;
                                constexpr float cv = B0.v[j][i][k];
                                if constexpr (cv != 0.0f) acc[k] = __fmaf_rn(cv, t2, acc[k]);
                            });
                        }
                    }
                }
                if constexpr (a1 || b1) {
                    constexpr bool e = eqk(A1, i, j, B1, j, i, 13);
                    if constexpr (e) {
                        float u = __fmaf_rn(wB1, p2, p1 * wA1);
                        sfor<13>([&](auto K) {
                            constexpr int k = decltype(K)::value;
                            constexpr float cv = A1.v[i][j][k];
                            if constexpr (cv != 0.0f) acc[9 + k] = __fmaf_rn(cv, u, acc[9 + k]);
                        });
                    } else {
                        if constexpr (a1) {
                            float t1 = p1 * wA1;
                            sfor<13>([&](auto K) {
                                constexpr int k = decltype(K)::value;
                                constexpr float cv = A1.v[i][j][k];
                                if constexpr (cv != 0.0f) acc[9 + k] = __fmaf_rn(cv, t1, acc[9 + k]);
                            });
                        }
                        if constexpr (b1) {
                            float t2 = p2 * wB1;
                            sfor<13>([&](auto K) {
                                constexpr int k = decltype(K)::value;
                                constexpr float cv = B1.v[j][i][k];
                                if constexpr (cv != 0.0f) acc[9 + k] = __fmaf_rn(cv, t2, acc[9 + k]);
                            });
                        }
                    }
                }
            }
        });
    });
}

// ---------------- kernel ----------------
constexpr int H = 768, W = 768;
constexpr int TX = 32, TY = 4;             // 128-thread tile
constexpr int NT = TX * TY;                // 128
constexpr int HTX = TX + 2, HTY = TY + 2;  // 34 x 6 haloed tile
constexpr int NPIX = HTX * HTY;            // 204
constexpr int NPAIR = 11;                  // 22 channels as 11 float2 pairs

__global__ void __launch_bounds__(NT, 7) eq_spatial_tp_kernel(
    const float* __restrict__ f4, const float* __restrict__ f6,
    const float* __restrict__ sw, const float* __restrict__ wp,
    float* __restrict__ out4, float* __restrict__ out6) {
    // channel-pair-major: tile[p][pix]; lane-consecutive pix -> conflict-free LDS.64
    __shared__ float2 tile[NPAIR * NPIX];

    const int tid = threadIdx.x;
    const int bx = blockIdx.x, by = blockIdx.y;
    const int gx0 = bx * TX - 1, gy0 = by * TY - 1;

    // Cooperative haloed-tile load with replicate clamping.
#pragma unroll 4
    for (int idx = tid; idx < NPAIR * NPIX; idx += NT) {
        int p = idx / NPIX, pix = idx - p * NPIX;
        int r = pix / HTX, c = pix - r * HTX;
        int gy = gy0 + r; gy = gy < 0 ? 0 : (gy > H - 1 ? H - 1 : gy);
        int gx = gx0 + c; gx = gx < 0 ? 0 : (gx > W - 1 ? W - 1 : gx);
        int g = gy * W + gx;
        int ch = 2 * p;
        float v0 = (ch < 9) ? f4[g * 9 + ch] : f6[g * 13 + (ch - 9)];
        float v1 = (ch + 1 < 9) ? f4[g * 9 + ch + 1] : f6[g * 13 + (ch + 1 - 9)];
        tile[idx] = make_float2(v0, v1);
    }
    __syncthreads();

    float2 swp[9];
#pragma unroll
    for (int q = 0; q < 9; ++q) {
        float s = sw[q];
        swp[q] = make_float2(s, s);
    }
    float wcomb[8];
#pragma unroll
    for (int p = 0; p < 8; ++p) wcomb[p] = 0.5f * wp[p];  // ALPHA = 1/sqrt(4)

    const int tx = tid & 31, ty = tid >> 5;

    // x1 = center features; x2 = weighted 3x3 neighbor average (packed f32x2)
    __align__(8) float x1[22], x2[22];
    float2* x1v = reinterpret_cast<float2*>(x1);
    float2* x2v = reinterpret_cast<float2*>(x2);
    {
        const int cpix = (ty + 1) * HTX + (tx + 1);
#pragma unroll
        for (int p = 0; p < NPAIR; ++p) {
            x1v[p] = tile[p * NPIX + cpix];
            x2v[p] = f2mul(swp[4], x1v[p]);
        }
    }
#pragma unroll
    for (int dy = 0; dy < 3; ++dy)
#pragma unroll
        for (int dx = 0; dx < 3; ++dx) {
            if (dy == 1 && dx == 1) continue;
            const int npix = (ty + dy) * HTX + (tx + dx);
            const float2 wq = swp[dy * 3 + dx];
#pragma unroll
            for (int p = 0; p < NPAIR; ++p)
                x2v[p] = f2fma(wq, tile[p * NPIX + npix], x2v[p]);
        }

    float acc[22];
#pragma unroll
    for (int k = 0; k < 22; ++k) acc[k] = x1[k];  // residual folded into init

    // merged path blocks: p = a*4 + b*2 + c
    tp_diag<4, 0>(x1, x2, acc, wcomb[0], wcomb[1]);
    tp_cross(x1, x2, acc, wcomb[2], wcomb[3], wcomb[4], wcomb[5]);
    tp_diag<6, 9>(x1, x2, acc, wcomb[6], wcomb[7]);

    // store (output layout: flat [N*9] then [N*13])
    const int gy = by * TY + ty, gx = bx * TX + tx;
    const int g = gy * W + gx;
#pragma unroll
    for (int k = 0; k < 9; ++k) out4[g * 9 + k] = acc[k];
#pragma unroll
    for (int k = 0; k < 13; ++k) out6[g * 13 + k] = acc[9 + k];
}

extern "C" void kernel_launch(void* const* d_in, const int* in_sizes, int n_in,
                              void* d_out, int out_size) {
    const float* f4 = (const float*)d_in[0];
    const float* f6 = (const float*)d_in[1];
    const float* sw = (const float*)d_in[2];  // spatial_weights [3,3]
    const float* wp = (const float*)d_in[3];  // w_paths [8]
    float* out = (float*)d_out;
    const size_t N = (size_t)H * W;

    dim3 grid(W / TX, H / TY);  // 24 x 192
    eq_spatial_tp_kernel<<<grid, NT>>>(f4, f6, sw, wp, out, out + N * 9);
}